// round 14
// baseline (speedup 1.0000x reference)
#include <cuda_runtime.h>
#include <math.h>

// ComplexEMA, fused single kernel.
//  - y via NORMALIZED biquad sections: v = z/b0 satisfies
//      v(t) = a1 v1 + a2 v2 + (x_t + c x_{t-1}),  c = b1/b0,
//    which is 3 FMA per harmonic per step (vs 4 for the raw biquad);
//    emission is acc = fma(b0, v, acc). Exact by linearity for b0 != 0;
//    |b0| clamped to 1e-12 (error <= 1e-12 * O(1), << 1e-3 tol).
//  - CHUNK=512 time-parallel chunks, WARM=96 zero-state warmup.
//  - Harmonics split 8/8 across adjacent lanes, shfl.xor(1) merges sums.
//  - h (final complex state) via (b,d,n)-parallel light blocks.
//  - R10 loop structure (no software prefetch: measured regression in R13).

#define NL    4096
#define ND    2048
#define NB    2
#define NN    16
#define NH    8                              // harmonics per thread
#define CHUNK 512
#define WARM  96
#define NCH   (NL / CHUNK)                   // 8
#define BLOCK 128
#define BQ_BLOCKS (NB * ND * NCH * 2 / BLOCK)  // 512
#define HT    192
#define H_BLOCKS  (NB * ND * NN / BLOCK)       // 512

__device__ __forceinline__ float sigf(float v) {
    return 1.0f / (1.0f + expf(-v));
}

__global__ void __launch_bounds__(BLOCK)
ema_fused(const float* __restrict__ x,
          const float* __restrict__ alpha,
          const float* __restrict__ delta,
          const float* __restrict__ theta,
          const float* __restrict__ gamma,
          const float* __restrict__ omega,
          float* __restrict__ out)
{
    if (blockIdx.x < BQ_BLOCKS) {
        // ------------------------- biquad y path -------------------------
        const int u     = blockIdx.x * BLOCK + threadIdx.x;
        const int half  = u & 1;             // which 8 harmonics
        const int b     = (u >> 1) & 1;
        const int d     = (u >> 2) & (ND - 1);
        const int chunk = u >> 13;           // 0..7, uniform per warp

        float a1[NH], a2[NH], cc[NH], w0[NH], vA[NH], vB[NH];
        {
            const float base = sigf(theta[d]) * 0.39269908169872414f;  // 2pi/16
            const int   nb   = half * NH;
            #pragma unroll
            for (int j = 0; j < NH; ++j) {
                const int   n  = nb + j;
                const float p  = sigf(alpha[d * NN + n]);
                const float dd = sigf(delta[d * NN + n]);
                const float qm = 1.0f - p * dd;
                float s, c;
                sincosf((float)(n + 1) * base, &s, &c);
                const float qr = qm * c, qi = qm * s;
                const float gr = gamma[(d * NN + n) * 2 + 0] * 0.25f;  // SCALE
                const float gi = gamma[(d * NN + n) * 2 + 1] * 0.25f;
                const float b0 = p * gr;
                const float b1 = -p * (gr * qr + gi * qi);
                const float b0c = copysignf(fmaxf(fabsf(b0), 1e-12f), b0);
                a1[j] = 2.0f * qr;
                a2[j] = -(qr * qr + qi * qi);
                cc[j] = b1 / b0c;            // x_{t-1} coefficient (normalized)
                w0[j] = b0c;                 // emission weight
                vA[j] = 0.0f;
                vB[j] = 0.0f;
            }
        }

        const size_t row = ((size_t)b * ND + d) * NL;
        const int    t0  = chunk * CHUNK;
        float x1 = 0.0f;

        // v(t) = a2*v2 + a1*v1 + (x_t + c*x_{t-1})   -- 3 FMA per harmonic
#define BQ_STEP(XT, ZN, ZO)                                         \
    {                                                               \
        const float xt_ = (XT);                                     \
        _Pragma("unroll")                                           \
        for (int j = 0; j < NH; ++j) {                              \
            float t = fmaf(cc[j], x1, xt_);                         \
            t = fmaf(a1[j], ZN[j], t);                              \
            ZO[j] = fmaf(a2[j], ZO[j], t);                          \
        }                                                           \
        x1 = xt_;                                                   \
    }

        // Emit: acc = fma(w0, v, acc) over this thread's 8 harmonics,
        // merged with the paired lane via shfl.xor(1).
#define BQ_STEP_EMIT(XT, ZN, ZO, YREF)                              \
    {                                                               \
        const float xt_ = (XT);                                     \
        float accA, accB;                                           \
        _Pragma("unroll")                                           \
        for (int j = 0; j < NH; ++j) {                              \
            float t = fmaf(cc[j], x1, xt_);                         \
            t = fmaf(a1[j], ZN[j], t);                              \
            const float v = fmaf(a2[j], ZO[j], t);                  \
            ZO[j] = v;                                              \
            if (j == 0)      accA = w0[j] * v;                      \
            else if (j == 1) accB = w0[j] * v;                      \
            else if (j & 1)  accB = fmaf(w0[j], v, accB);           \
            else             accA = fmaf(w0[j], v, accA);           \
        }                                                           \
        x1 = xt_;                                                   \
        const float part  = accA + accB;                            \
        const float other = __shfl_xor_sync(0xffffffffu, part, 1);  \
        (YREF) = fmaf(omega_d, xt_, part + other);                  \
    }

        // Warmup from zero state (chunk 0 skips; chunk uniform per warp).
        if (chunk != 0) {
            x1 = x[row + t0 - WARM - 1];
            const float4* xw = (const float4*)(x + row + (t0 - WARM));
            #pragma unroll 1
            for (int i = 0; i < WARM / 4; ++i) {
                const float4 xv = xw[i];
                BQ_STEP(xv.x, vA, vB);
                BQ_STEP(xv.y, vB, vA);
                BQ_STEP(xv.z, vA, vB);
                BQ_STEP(xv.w, vB, vA);
            }
        }

        // Main chunk: update + emit y. Paired lanes alternate float4 stores.
        // (WARM%4==0 keeps ping-pong parity.)
        {
            const float omega_d = omega[d];
            const float4* xm = (const float4*)(x + row + t0);
            float4*       yo = (float4*)(out + row + t0);
            #pragma unroll 1
            for (int i = 0; i < CHUNK / 4; ++i) {
                const float4 xv = xm[i];
                float4 yv;
                BQ_STEP_EMIT(xv.x, vA, vB, yv.x);
                BQ_STEP_EMIT(xv.y, vB, vA, yv.y);
                BQ_STEP_EMIT(xv.z, vA, vB, yv.z);
                BQ_STEP_EMIT(xv.w, vB, vA, yv.w);
                if (((i ^ half) & 1) == 0) yo[i] = yv;
            }
        }
#undef BQ_STEP
#undef BQ_STEP_EMIT
    } else {
        // ----------------- final-state h path, (b,d,n)-parallel -----------
        const int htid = (blockIdx.x - BQ_BLOCKS) * BLOCK + threadIdx.x;
        const int n = htid & (NN - 1);
        const int d = (htid >> 4) & (ND - 1);
        const int b = htid >> 15;

        float qr, qi, pv;
        {
            const float base = sigf(theta[d]) * 0.39269908169872414f;
            const float p  = sigf(alpha[d * NN + n]);
            const float dd = sigf(delta[d * NN + n]);
            const float qm = 1.0f - p * dd;
            float s, c;
            sincosf((float)(n + 1) * base, &s, &c);
            qr = qm * c;
            qi = qm * s;
            pv = p;
        }

        const size_t row = ((size_t)b * ND + d) * NL;
        float hr = 0.0f, hi = 0.0f;

        const float4* xh = (const float4*)(x + row + (NL - HT));
        float4 xv = xh[0];
        #pragma unroll 1
        for (int i = 0; i < HT / 4; ++i) {
            float4 xn = xv;
            if (i + 1 < HT / 4) xn = xh[i + 1];
            #pragma unroll
            for (int e = 0; e < 4; ++e) {
                const float xt = (e == 0) ? xv.x : (e == 1) ? xv.y
                               : (e == 2) ? xv.z : xv.w;
                const float px  = pv * xt;
                const float t1  = fmaf(-qi, hi, px);
                const float nhr = fmaf(qr, hr, t1);
                const float nhi = fmaf(qi, hr, qr * hi);
                hr = nhr;
                hi = nhi;
            }
            xv = xn;
        }

        float* hout = out + (size_t)NB * ND * NL
                          + (((size_t)b * ND + d) * NN + n) * 2;
        hout[0] = hr;
        hout[1] = hi;
    }
}

extern "C" void kernel_launch(void* const* d_in, const int* in_sizes, int n_in,
                              void* d_out, int out_size)
{
    const float* x     = (const float*)d_in[0];
    const float* alpha = (const float*)d_in[1];
    const float* delta = (const float*)d_in[2];
    const float* theta = (const float*)d_in[3];
    const float* gamma = (const float*)d_in[4];
    const float* omega = (const float*)d_in[5];
    float* out = (float*)d_out;

    ema_fused<<<BQ_BLOCKS + H_BLOCKS, BLOCK>>>(x, alpha, delta, theta, gamma,
                                               omega, out);
}

// round 17
// speedup vs baseline: 1.5819x; 1.5819x over previous
#include <cuda_runtime.h>
#include <math.h>

// ComplexEMA, fused single kernel. R10 structure exactly, with ONE change:
// normalized biquad sections.
//   v = z/b0 :  v(t) = a1 v1 + a2 v2 + (x_t + c x_{t-1}),  c = b1/b0
//   emit      :  acc = fma(b0, v, acc)
// 4 fma-pipe ops per harmonic per emitted sample (vs 5 raw), 3 in warmup
// (vs 4). Exact by linearity; |b0| clamped to 1e-12 (error ~1e-12, << tol;
// no overflow: |v| stays far below fp32 max).
//  - CHUNK=512 time-parallel chunks, WARM=96 zero-state warmup.
//  - Harmonics split 8/8 across adjacent lanes, shfl.xor(1) merges sums.
//  - h (final complex state) via (b,d,n)-parallel light blocks.
//  - NO software prefetch, NO acc-init tricks (both measured regressions).

#define NL    4096
#define ND    2048
#define NB    2
#define NN    16
#define NH    8                              // harmonics per thread
#define CHUNK 512
#define WARM  96
#define NCH   (NL / CHUNK)                   // 8
#define BLOCK 128
#define BQ_BLOCKS (NB * ND * NCH * 2 / BLOCK)  // 512
#define HT    192
#define H_BLOCKS  (NB * ND * NN / BLOCK)       // 512

__device__ __forceinline__ float sigf(float v) {
    return 1.0f / (1.0f + expf(-v));
}

__global__ void __launch_bounds__(BLOCK)
ema_fused(const float* __restrict__ x,
          const float* __restrict__ alpha,
          const float* __restrict__ delta,
          const float* __restrict__ theta,
          const float* __restrict__ gamma,
          const float* __restrict__ omega,
          float* __restrict__ out)
{
    if (blockIdx.x < BQ_BLOCKS) {
        // ------------------------- biquad y path -------------------------
        const int u     = blockIdx.x * BLOCK + threadIdx.x;
        const int half  = u & 1;             // which 8 harmonics
        const int b     = (u >> 1) & 1;
        const int d     = (u >> 2) & (ND - 1);
        const int chunk = u >> 13;           // 0..7, uniform per warp

        float a1[NH], a2[NH], cc[NH], w0[NH], vA[NH], vB[NH];
        {
            const float base = sigf(theta[d]) * 0.39269908169872414f;  // 2pi/16
            const int   nb   = half * NH;
            #pragma unroll
            for (int j = 0; j < NH; ++j) {
                const int   n  = nb + j;
                const float p  = sigf(alpha[d * NN + n]);
                const float dd = sigf(delta[d * NN + n]);
                const float qm = 1.0f - p * dd;
                float s, c;
                sincosf((float)(n + 1) * base, &s, &c);
                const float qr = qm * c, qi = qm * s;
                const float gr = gamma[(d * NN + n) * 2 + 0] * 0.25f;  // SCALE
                const float gi = gamma[(d * NN + n) * 2 + 1] * 0.25f;
                const float b0 = p * gr;
                const float b1 = -p * (gr * qr + gi * qi);
                const float b0c = copysignf(fmaxf(fabsf(b0), 1e-12f), b0);
                a1[j] = 2.0f * qr;
                a2[j] = -(qr * qr + qi * qi);
                cc[j] = b1 / b0c;
                w0[j] = b0c;
                vA[j] = 0.0f;
                vB[j] = 0.0f;
            }
        }

        const size_t row = ((size_t)b * ND + d) * NL;
        const int    t0  = chunk * CHUNK;
        float x1 = 0.0f;

        // v(t) = a2*v2 + a1*v1 + fma(c, x_{t-1}, x_t)  -- 3 FMA per harmonic
#define BQ_STEP(XT, ZN, ZO)                                         \
    {                                                               \
        const float xt_ = (XT);                                     \
        _Pragma("unroll")                                           \
        for (int j = 0; j < NH; ++j) {                              \
            float t = fmaf(cc[j], x1, xt_);                         \
            t = fmaf(a1[j], ZN[j], t);                              \
            ZO[j] = fmaf(a2[j], ZO[j], t);                          \
        }                                                           \
        x1 = xt_;                                                   \
    }

        // Emit: acc = fma(w0, v, acc); merged with paired lane (shfl.xor 1).
#define BQ_STEP_EMIT(XT, ZN, ZO, YREF)                              \
    {                                                               \
        const float xt_ = (XT);                                     \
        float accA = 0.0f, accB = 0.0f;                             \
        _Pragma("unroll")                                           \
        for (int j = 0; j < NH; ++j) {                              \
            float t = fmaf(cc[j], x1, xt_);                         \
            t = fmaf(a1[j], ZN[j], t);                              \
            const float v = fmaf(a2[j], ZO[j], t);                  \
            ZO[j] = v;                                              \
            if (j & 1) accB = fmaf(w0[j], v, accB);                 \
            else       accA = fmaf(w0[j], v, accA);                 \
        }                                                           \
        x1 = xt_;                                                   \
        const float part  = accA + accB;                            \
        const float other = __shfl_xor_sync(0xffffffffu, part, 1);  \
        (YREF) = fmaf(omega_d, xt_, part + other);                  \
    }

        // Warmup from zero state (chunk 0 skips; chunk uniform per warp).
        if (chunk != 0) {
            x1 = x[row + t0 - WARM - 1];
            const float4* xw = (const float4*)(x + row + (t0 - WARM));
            #pragma unroll 1
            for (int i = 0; i < WARM / 4; ++i) {
                const float4 xv = xw[i];
                BQ_STEP(xv.x, vA, vB);
                BQ_STEP(xv.y, vB, vA);
                BQ_STEP(xv.z, vA, vB);
                BQ_STEP(xv.w, vB, vA);
            }
        }

        // Main chunk: update + emit y. Paired lanes alternate float4 stores.
        // (WARM%4==0 keeps ping-pong parity.)
        {
            const float omega_d = omega[d];
            const float4* xm = (const float4*)(x + row + t0);
            float4*       yo = (float4*)(out + row + t0);
            #pragma unroll 1
            for (int i = 0; i < CHUNK / 4; ++i) {
                const float4 xv = xm[i];
                float4 yv;
                BQ_STEP_EMIT(xv.x, vA, vB, yv.x);
                BQ_STEP_EMIT(xv.y, vB, vA, yv.y);
                BQ_STEP_EMIT(xv.z, vA, vB, yv.z);
                BQ_STEP_EMIT(xv.w, vB, vA, yv.w);
                if (((i ^ half) & 1) == 0) yo[i] = yv;
            }
        }
#undef BQ_STEP
#undef BQ_STEP_EMIT
    } else {
        // ----------------- final-state h path, (b,d,n)-parallel -----------
        const int htid = (blockIdx.x - BQ_BLOCKS) * BLOCK + threadIdx.x;
        const int n = htid & (NN - 1);
        const int d = (htid >> 4) & (ND - 1);
        const int b = htid >> 15;

        float qr, qi, pv;
        {
            const float base = sigf(theta[d]) * 0.39269908169872414f;
            const float p  = sigf(alpha[d * NN + n]);
            const float dd = sigf(delta[d * NN + n]);
            const float qm = 1.0f - p * dd;
            float s, c;
            sincosf((float)(n + 1) * base, &s, &c);
            qr = qm * c;
            qi = qm * s;
            pv = p;
        }

        const size_t row = ((size_t)b * ND + d) * NL;
        float hr = 0.0f, hi = 0.0f;

        const float4* xh = (const float4*)(x + row + (NL - HT));
        float4 xv = xh[0];
        #pragma unroll 1
        for (int i = 0; i < HT / 4; ++i) {
            float4 xn = xv;
            if (i + 1 < HT / 4) xn = xh[i + 1];
            #pragma unroll
            for (int e = 0; e < 4; ++e) {
                const float xt = (e == 0) ? xv.x : (e == 1) ? xv.y
                               : (e == 2) ? xv.z : xv.w;
                const float px  = pv * xt;
                const float t1  = fmaf(-qi, hi, px);
                const float nhr = fmaf(qr, hr, t1);
                const float nhi = fmaf(qi, hr, qr * hi);
                hr = nhr;
                hi = nhi;
            }
            xv = xn;
        }

        float* hout = out + (size_t)NB * ND * NL
                          + (((size_t)b * ND + d) * NN + n) * 2;
        hout[0] = hr;
        hout[1] = hi;
    }
}

extern "C" void kernel_launch(void* const* d_in, const int* in_sizes, int n_in,
                              void* d_out, int out_size)
{
    const float* x     = (const float*)d_in[0];
    const float* alpha = (const float*)d_in[1];
    const float* delta = (const float*)d_in[2];
    const float* theta = (const float*)d_in[3];
    const float* gamma = (const float*)d_in[4];
    const float* omega = (const float*)d_in[5];
    float* out = (float*)d_out;

    ema_fused<<<BQ_BLOCKS + H_BLOCKS, BLOCK>>>(x, alpha, delta, theta, gamma,
                                               omega, out);
}